// round 16
// baseline (speedup 1.0000x reference)
#include <cuda_runtime.h>
#include <cuda_fp16.h>
#include <cstdint>

// Correlation via parity-split banded Gram matrices on fp16 mma.sync,
// j-batching (3 j per CTA share the A image), fp16 staging, 20 warps.
// out[b, i*41+j, y, x] = (1/576)*sum_c in1[b,c,y,x]*in2[b,c,y-2(j-10),x-2(i-10)]
//
// prep: in1 rows -> parity-permuted A images (2*80 rows x 128B fp16 K-major,
//   SW128). in2 rows -> B images (2*120 rows, u-pad +-30 baked in).
// main: CTA=(jg,y,b), 640 thr = 20 warps = (parity p, strip s, n-half h).
//   Warp: m16 x 28-col half-band x k64 (h=0: 4 n8-tiles, h=1: 3).
//   Stage fp16 (pitch 58, overlays B) -> branch-free diagonal gather.

#define D41 41
#define HH 96
#define WW 160
#define CC 64
#define OSTRI (D41*HH*WW)

#define AROWB 20480           // A image: 160 rows x 128B
#define BROWB 30720           // B image: 240 rows x 128B
#define A_TOT ((size_t)4 * HH * AROWB)

#define SM_A   0              // [0, 20480) persistent per CTA
#define SM_B   20480          // B image [20480, 51200); fp16 stage overlays
#define SMEM_BYTES 51200
#define PITCH 58              // stage pitch in halfs; stage = 160*58*2 = 18560B

__device__ __align__(1024) unsigned char g_scr[A_TOT + (size_t)4 * HH * BROWB];

__device__ __forceinline__ uint32_t swz(uint32_t o) { return o ^ ((o >> 3) & 0x70); }

__device__ __forceinline__ uint32_t smem_u32(const void* p) {
    uint32_t a;
    asm("{ .reg .u64 t; cvta.to.shared.u64 t, %1; cvt.u32.u64 %0, t; }"
        : "=r"(a) : "l"(p));
    return a;
}
__device__ __forceinline__ void ldsm4(uint32_t* r, uint32_t a) {
    asm volatile("ldmatrix.sync.aligned.m8n8.x4.shared.b16 {%0,%1,%2,%3}, [%4];"
                 : "=r"(r[0]), "=r"(r[1]), "=r"(r[2]), "=r"(r[3]) : "r"(a));
}
__device__ __forceinline__ void ldsm2(uint32_t* r, uint32_t a) {
    asm volatile("ldmatrix.sync.aligned.m8n8.x2.shared.b16 {%0,%1}, [%2];"
                 : "=r"(r[0]), "=r"(r[1]) : "r"(a));
}
__device__ __forceinline__ void mma16816(float* d, const uint32_t* a, const uint32_t* b) {
    asm volatile(
        "mma.sync.aligned.m16n8k16.row.col.f32.f16.f16.f32 "
        "{%0,%1,%2,%3},{%4,%5,%6,%7},{%8,%9},{%0,%1,%2,%3};"
        : "+f"(d[0]), "+f"(d[1]), "+f"(d[2]), "+f"(d[3])
        : "r"(a[0]), "r"(a[1]), "r"(a[2]), "r"(a[3]), "r"(b[0]), "r"(b[1]));
}

// ---------- prep: fp32 rows -> parity-permuted swizzled fp16 images ----------
__global__ void __launch_bounds__(256)
prep_kernel(const float* __restrict__ in1, const float* __restrict__ in2)
{
    __shared__ uint32_t th[160 * 33];
    const int y = blockIdx.x, b = blockIdx.y, w = blockIdx.z;
    const float* src = (w ? in2 : in1) + ((size_t)(b * CC) * HH + y) * WW;
    unsigned char* dst = w ? (g_scr + A_TOT + (size_t)(b * HH + y) * BROWB)
                           : (g_scr + (size_t)(b * HH + y) * AROWB);
    const int t = threadIdx.x;

    if (t < WW) {
#pragma unroll 4
        for (int c2 = 0; c2 < 32; ++c2) {
            float v0 = src[(size_t)(2 * c2) * (HH * WW) + t];
            float v1 = src[(size_t)(2 * c2 + 1) * (HH * WW) + t];
            __half2 h = __floats2half2_rn(v0, v1);
            th[t * 33 + c2] = *reinterpret_cast<uint32_t*>(&h);
        }
    }
    __syncthreads();

    if (w == 0) {
        for (int idx = t; idx < 160 * 32; idx += 256) {
            int x = idx >> 5, c2 = idx & 31;
            int row = (x & 1) * 80 + (x >> 1);
            *reinterpret_cast<uint32_t*>(dst + swz((uint32_t)(row * 128 + c2 * 4))) =
                th[x * 33 + c2];
        }
    } else {
        uint32_t* d32 = reinterpret_cast<uint32_t*>(dst);
        for (int idx = t; idx < 80 * 32; idx += 256) {
            int r = idx >> 5, c2 = idx & 31;
            int p = (r >= 40), q = r - p * 40;
            int v = (q < 30) ? q : (q + 80);
            d32[(p * 120 + v) * 32 + c2] = 0;     // whole-row zero: swz-invariant
        }
        for (int idx = t; idx < 160 * 32; idx += 256) {
            int x = idx >> 5, c2 = idx & 31;
            int row = (x & 1) * 120 + (x >> 1) + 30;
            *reinterpret_cast<uint32_t*>(dst + swz((uint32_t)(row * 128 + c2 * 4))) =
                th[x * 33 + c2];
        }
    }
}

// ---------- main ----------
extern __shared__ __align__(1024) unsigned char smem[];

__global__ void __launch_bounds__(640, 2)
corr_main(float* __restrict__ out)
{
    const int jg = blockIdx.x, y = blockIdx.y, b = blockIdx.z;
    const int tid = threadIdx.x;
    const int wid = tid >> 5, lid = tid & 31;

    // ---- A image: copy once (raw, pre-swizzled) ----
    {
        const uint4* asrc = reinterpret_cast<const uint4*>(
            g_scr + (size_t)(b * HH + y) * AROWB);
        uint4* dA = reinterpret_cast<uint4*>(smem + SM_A);
#pragma unroll
        for (int it = 0; it < 2; ++it) dA[tid + 640 * it] = asrc[tid + 640 * it];
    }

    const uint32_t sb = smem_u32(smem);
    const int p = wid & 1;                   // parity
    const int u = wid >> 1;                  // 0..9
    const int s = u % 5;                     // strip (rows 16s..16s+16 of 80)
    const int h = u / 5;                     // n-half: tiles [4h, 4h+4-h)

    const uint32_t xr = (uint32_t)((lid & 7) << 4);
    const uint32_t aRow = sb + SM_A +
        (uint32_t)((p * 80 + 16 * s + (lid & 15)) * 128);
    const uint32_t caA = (uint32_t)(16 * (lid >> 4));
    // B: warp's band rows start at 16s + 32h
    const uint32_t bRowA = sb + SM_B +
        (uint32_t)((p * 120 + 16 * s + 32 * h + (lid & 7) + 8 * (lid >> 4)) * 128);
    const uint32_t bRowB = sb + SM_B +
        (uint32_t)((p * 120 + 16 * s + 32 * h + 16 +
                    (h ? (lid & 7) : ((lid & 7) + 8 * (lid >> 4)))) * 128);
    const uint32_t caB = (uint32_t)(16 * ((lid >> 3) & 1));

    __half* stg = reinterpret_cast<__half*>(smem + SM_B);
    const int njj = (jg == 13) ? 2 : 3;

#pragma unroll 1
    for (int jj = 0; jj < njj; ++jj) {
        const int j = 3 * jg + jj;
        const int y2 = y - 2 * (j - 10);
        const bool valid = (y2 >= 0) && (y2 < HH);
        const int obase = ((b * (D41 * D41) + j) * HH + y) * WW;

        __syncthreads();          // stage (prev j) fully read; A copy done (jj=0)

        if (valid) {
            const uint4* bsrc = reinterpret_cast<const uint4*>(
                g_scr + A_TOT + (size_t)(b * HH + y2) * BROWB);
            uint4* dB = reinterpret_cast<uint4*>(smem + SM_B);
#pragma unroll
            for (int it = 0; it < 3; ++it) dB[tid + 640 * it] = bsrc[tid + 640 * it];
        }
        __syncthreads();

        if (valid) {
            float acc[4][4];
#pragma unroll
            for (int t = 0; t < 4; ++t)
#pragma unroll
                for (int r = 0; r < 4; ++r) acc[t][r] = 0.f;

#pragma unroll
            for (int k = 0; k < 4; ++k) {
                const uint32_t cA = (caA + 32u * k) ^ xr;
                const uint32_t cB = (caB + 32u * k) ^ xr;
                uint32_t a[4];
                ldsm4(a, aRow + cA);
                uint32_t bf[8];
                ldsm4(bf, bRowA + cB);
                if (h == 0) {
                    ldsm4(bf + 4, bRowB + cB);
                    mma16816(acc[0], a, bf);
                    mma16816(acc[1], a, bf + 2);
                    mma16816(acc[2], a, bf + 4);
                    mma16816(acc[3], a, bf + 6);
                } else {
                    ldsm2(bf + 4, bRowB + cB);
                    mma16816(acc[0], a, bf);
                    mma16816(acc[1], a, bf + 2);
                    mma16816(acc[2], a, bf + 4);
                }
            }

            __syncthreads();      // B image fully consumed; stage may overwrite

            const int g = lid >> 2;
            const int n0 = 2 * (lid & 3);
            const int r0 = p * 80 + 16 * s + g;
            const int nt = 4 - h;
#pragma unroll
            for (int t = 0; t < 4; ++t) {
                if (t >= nt) break;
                const int n = 8 * (4 * h + t) + n0;
                __half2 lo = __floats2half2_rn(acc[t][0], acc[t][1]);
                __half2 hi = __floats2half2_rn(acc[t][2], acc[t][3]);
                *reinterpret_cast<__half2*>(stg + r0 * PITCH + n) = lo;
                *reinterpret_cast<__half2*>(stg + (r0 + 8) * PITCH + n) = hi;
            }
            __syncthreads();

            // gather: x = 2xh+p; col = (xh&15) + 40 - i; row = p*80 + xh
            const int x = tid % 160;
            const int q = tid / 160;                 // 0..3
            const int ilo = q ? (11 + 10 * (q - 1)) : 0;
            const int ihi = 11 + 10 * q;
            const int xh = x >> 1;
            const float scl = 1.0f / 576.0f;
            const __half* row = stg + ((x & 1) * 80 + xh) * PITCH + (xh & 15) + 40;
            float* op = out + obase + x;
#pragma unroll 1
            for (int i = ilo; i < ihi; ++i)
                op[i * OSTRI] = __half2float(row[-i]) * scl;
        } else {
            __syncthreads();      // match the two syncs of the valid path
            __syncthreads();
            const float4 z = make_float4(0.f, 0.f, 0.f, 0.f);
            for (int idx = tid; idx < D41 * (WW / 4); idx += 640) {
                int i = idx / (WW / 4), v = idx - i * (WW / 4);
                *reinterpret_cast<float4*>(out + obase + i * OSTRI + v * 4) = z;
            }
        }
    }
}

extern "C" void kernel_launch(void* const* d_in, const int* in_sizes, int n_in,
                              void* d_out, int out_size) {
    const float* in1 = (const float*)d_in[0];
    const float* in2 = (const float*)d_in[1];
    float* out = (float*)d_out;

    cudaFuncSetAttribute(corr_main,
                         cudaFuncAttributeMaxDynamicSharedMemorySize, SMEM_BYTES);

    prep_kernel<<<dim3(HH, 4, 2), 256>>>(in1, in2);
    corr_main<<<dim3(14, HH, 4), 640, SMEM_BYTES>>>(out);
}

// round 17
// speedup vs baseline: 1.2201x; 1.2201x over previous
#include <cuda_runtime.h>
#include <cuda_fp16.h>
#include <cstdint>

// Correlation via parity-split banded Gram matrices on fp16 mma.sync,
// j-batching (3 j per CTA share the A image), fp16 staging.
// out[b, i*41+j, y, x] = (1/576)*sum_c in1[b,c,y,x]*in2[b,c,y-2(j-10),x-2(i-10)]
//
// prep: in1 rows -> parity-permuted A images (2*80 rows x 128B fp16 K-major,
//   SW128). in2 rows -> B images (2*120 rows, u-pad +-30 baked in).
// main: CTA=(jg,y,b), 320 thr = 10 warps = (parity p, strip s). Per j:
//   copy B image, warp does m16 x 56-col band x k64 (7 n8 x 4 k).
//   Stage fp16 (pitch 58, overlays B) -> branch-free diagonal gather.

#define D41 41
#define HH 96
#define WW 160
#define CC 64
#define OSTRI (D41*HH*WW)

#define AROWB 20480           // A image: 160 rows x 128B
#define BROWB 30720           // B image: 240 rows x 128B
#define A_TOT ((size_t)4 * HH * AROWB)

#define SM_A   0              // [0, 20480) persistent per CTA
#define SM_B   20480          // B image [20480, 51200); fp16 stage overlays
#define SMEM_BYTES 51200
#define PITCH 58              // stage pitch in halfs; stage = 160*58*2 = 18560B

__device__ __align__(1024) unsigned char g_scr[A_TOT + (size_t)4 * HH * BROWB];

__device__ __forceinline__ uint32_t swz(uint32_t o) { return o ^ ((o >> 3) & 0x70); }

__device__ __forceinline__ uint32_t smem_u32(const void* p) {
    uint32_t a;
    asm("{ .reg .u64 t; cvta.to.shared.u64 t, %1; cvt.u32.u64 %0, t; }"
        : "=r"(a) : "l"(p));
    return a;
}
__device__ __forceinline__ void ldsm4(uint32_t* r, uint32_t a) {
    asm volatile("ldmatrix.sync.aligned.m8n8.x4.shared.b16 {%0,%1,%2,%3}, [%4];"
                 : "=r"(r[0]), "=r"(r[1]), "=r"(r[2]), "=r"(r[3]) : "r"(a));
}
__device__ __forceinline__ void ldsm2(uint32_t* r, uint32_t a) {
    asm volatile("ldmatrix.sync.aligned.m8n8.x2.shared.b16 {%0,%1}, [%2];"
                 : "=r"(r[0]), "=r"(r[1]) : "r"(a));
}
__device__ __forceinline__ void mma16816(float* d, const uint32_t* a, const uint32_t* b) {
    asm volatile(
        "mma.sync.aligned.m16n8k16.row.col.f32.f16.f16.f32 "
        "{%0,%1,%2,%3},{%4,%5,%6,%7},{%8,%9},{%0,%1,%2,%3};"
        : "+f"(d[0]), "+f"(d[1]), "+f"(d[2]), "+f"(d[3])
        : "r"(a[0]), "r"(a[1]), "r"(a[2]), "r"(a[3]), "r"(b[0]), "r"(b[1]));
}

// ---------- prep: fp32 rows -> parity-permuted swizzled fp16 images ----------
__global__ void __launch_bounds__(256)
prep_kernel(const float* __restrict__ in1, const float* __restrict__ in2)
{
    __shared__ uint32_t th[160 * 33];
    const int y = blockIdx.x, b = blockIdx.y, w = blockIdx.z;
    const float* src = (w ? in2 : in1) + ((size_t)(b * CC) * HH + y) * WW;
    unsigned char* dst = w ? (g_scr + A_TOT + (size_t)(b * HH + y) * BROWB)
                           : (g_scr + (size_t)(b * HH + y) * AROWB);
    const int t = threadIdx.x;

    if (t < WW) {
#pragma unroll 4
        for (int c2 = 0; c2 < 32; ++c2) {
            float v0 = src[(size_t)(2 * c2) * (HH * WW) + t];
            float v1 = src[(size_t)(2 * c2 + 1) * (HH * WW) + t];
            __half2 h = __floats2half2_rn(v0, v1);
            th[t * 33 + c2] = *reinterpret_cast<uint32_t*>(&h);
        }
    }
    __syncthreads();

    if (w == 0) {
        for (int idx = t; idx < 160 * 32; idx += 256) {
            int x = idx >> 5, c2 = idx & 31;
            int row = (x & 1) * 80 + (x >> 1);
            *reinterpret_cast<uint32_t*>(dst + swz((uint32_t)(row * 128 + c2 * 4))) =
                th[x * 33 + c2];
        }
    } else {
        uint32_t* d32 = reinterpret_cast<uint32_t*>(dst);
        for (int idx = t; idx < 80 * 32; idx += 256) {
            int r = idx >> 5, c2 = idx & 31;
            int p = (r >= 40), q = r - p * 40;
            int v = (q < 30) ? q : (q + 80);
            d32[(p * 120 + v) * 32 + c2] = 0;     // whole-row zero: swz-invariant
        }
        for (int idx = t; idx < 160 * 32; idx += 256) {
            int x = idx >> 5, c2 = idx & 31;
            int row = (x & 1) * 120 + (x >> 1) + 30;
            *reinterpret_cast<uint32_t*>(dst + swz((uint32_t)(row * 128 + c2 * 4))) =
                th[x * 33 + c2];
        }
    }
}

// ---------- main ----------
extern __shared__ __align__(1024) unsigned char smem[];

__global__ void __launch_bounds__(320, 3)
corr_main(float* __restrict__ out)
{
    const int jg = blockIdx.x, y = blockIdx.y, b = blockIdx.z;
    const int tid = threadIdx.x;
    const int wid = tid >> 5, lid = tid & 31;

    // ---- A image: copy once (raw, pre-swizzled) ----
    {
        const uint4* asrc = reinterpret_cast<const uint4*>(
            g_scr + (size_t)(b * HH + y) * AROWB);
        uint4* dA = reinterpret_cast<uint4*>(smem + SM_A);
#pragma unroll
        for (int it = 0; it < 4; ++it) dA[tid + 320 * it] = asrc[tid + 320 * it];
    }

    const uint32_t sb = smem_u32(smem);
    const int s = wid >> 1;                  // strip 0..4 (rows 16s..16s+16)
    const int p = wid & 1;                   // parity

    const uint32_t xr = (uint32_t)((lid & 7) << 4);
    const uint32_t aRow = sb + SM_A +
        (uint32_t)((p * 80 + 16 * s + (lid & 15)) * 128);
    const uint32_t caA = (uint32_t)(16 * (lid >> 4));
    const uint32_t bRow = sb + SM_B +
        (uint32_t)((p * 120 + 16 * s + (lid & 7) + 8 * (lid >> 4)) * 128);
    const uint32_t bRow2 = sb + SM_B +
        (uint32_t)((p * 120 + 16 * s + 48 + (lid & 7)) * 128);
    const uint32_t caB = (uint32_t)(16 * ((lid >> 3) & 1));

    __half* stg = reinterpret_cast<__half*>(smem + SM_B);
    const int njj = (jg == 13) ? 2 : 3;

#pragma unroll 1
    for (int jj = 0; jj < njj; ++jj) {
        const int j = 3 * jg + jj;
        const int y2 = y - 2 * (j - 10);
        const bool valid = (y2 >= 0) && (y2 < HH);
        const int obase = ((b * (D41 * D41) + j) * HH + y) * WW;

        __syncthreads();          // stage (prev j) fully read; A copy done (jj=0)

        if (valid) {
            const uint4* bsrc = reinterpret_cast<const uint4*>(
                g_scr + A_TOT + (size_t)(b * HH + y2) * BROWB);
            uint4* dB = reinterpret_cast<uint4*>(smem + SM_B);
#pragma unroll
            for (int it = 0; it < 6; ++it) dB[tid + 320 * it] = bsrc[tid + 320 * it];
        }
        __syncthreads();

        if (valid) {
            float acc[7][4];
#pragma unroll
            for (int t = 0; t < 7; ++t)
#pragma unroll
                for (int r = 0; r < 4; ++r) acc[t][r] = 0.f;

#pragma unroll
            for (int k = 0; k < 4; ++k) {
                const uint32_t cA = (caA + 32u * k) ^ xr;
                const uint32_t cB = (caB + 32u * k) ^ xr;
                uint32_t a[4];
                ldsm4(a, aRow + cA);
                uint32_t bf[14];
#pragma unroll
                for (int u = 0; u < 3; ++u)
                    ldsm4(bf + 4 * u, bRow + (uint32_t)(u * 2048) + cB);
                ldsm2(bf + 12, bRow2 + cB);
#pragma unroll
                for (int t = 0; t < 7; ++t) mma16816(acc[t], a, bf + 2 * t);
            }

            __syncthreads();      // B image fully consumed; stage may overwrite

            const int g = lid >> 2;
            const int n0 = 2 * (lid & 3);
            const int r0 = p * 80 + 16 * s + g;
#pragma unroll
            for (int t = 0; t < 7; ++t) {
                const int n = 8 * t + n0;
                __half2 lo = __floats2half2_rn(acc[t][0], acc[t][1]);
                __half2 hi = __floats2half2_rn(acc[t][2], acc[t][3]);
                *reinterpret_cast<__half2*>(stg + r0 * PITCH + n) = lo;
                *reinterpret_cast<__half2*>(stg + (r0 + 8) * PITCH + n) = hi;
            }
            __syncthreads();

            // gather: x = 2xh+p; col = (xh&15) + 40 - i; row = p*80 + xh
            const int x = (tid < 160) ? tid : (tid - 160);
            const int ilo = (tid < 160) ? 0 : 21;
            const int ihi = (tid < 160) ? 21 : 41;
            const int xh = x >> 1;
            const float scl = 1.0f / 576.0f;
            const __half* row = stg + ((x & 1) * 80 + xh) * PITCH + (xh & 15) + 40;
            float* op = out + obase + x;
#pragma unroll 1
            for (int i = ilo; i < ihi; ++i)
                op[i * OSTRI] = __half2float(row[-i]) * scl;
        } else {
            __syncthreads();      // match the two syncs of the valid path
            __syncthreads();
            const float4 z = make_float4(0.f, 0.f, 0.f, 0.f);
            for (int idx = tid; idx < D41 * (WW / 4); idx += 320) {
                int i = idx / (WW / 4), v = idx - i * (WW / 4);
                *reinterpret_cast<float4*>(out + obase + i * OSTRI + v * 4) = z;
            }
        }
    }
}

extern "C" void kernel_launch(void* const* d_in, const int* in_sizes, int n_in,
                              void* d_out, int out_size) {
    const float* in1 = (const float*)d_in[0];
    const float* in2 = (const float*)d_in[1];
    float* out = (float*)d_out;

    cudaFuncSetAttribute(corr_main,
                         cudaFuncAttributeMaxDynamicSharedMemorySize, SMEM_BYTES);

    prep_kernel<<<dim3(HH, 4, 2), 256>>>(in1, in2);
    corr_main<<<dim3(14, HH, 4), 320, SMEM_BYTES>>>(out);
}